// round 2
// baseline (speedup 1.0000x reference)
#include <cuda_runtime.h>
#include <math.h>

// Problem constants
#define NNODES 32768
#define DIN    128
#define DD     256
#define D2     512
#define EDGES  131072
#define BGR    256
#define EPG    512
#define NPG    128
#define NRES   256
#define BN_EPS 1e-5f

// Output layout (float32, 524288 elems)
#define OFF_CEI   0
#define OFF_CW    131072
#define OFF_DEI   196608
#define OFF_DW    327680
#define OFF_PRED  393216

// ---------------- scratch (device globals; no allocation) ----------------
__device__ float g_h1[NNODES * DIN];
__device__ float g_z [NNODES * D2];
__device__ float g_o1[NNODES * DD];
__device__ float g_h2[NNODES * DD];
__device__ float g_part[2 * 256 * 512];   // [sum | sumsq], stride 512, 256 m-blocks
#define PART_SQ (256 * 512)
__device__ float g_scale[512];
__device__ float g_shift[512];
__device__ float g_sa[NNODES];
__device__ float g_sc[NNODES];

// ---------------- f32x2 packed-FMA helpers ----------------
__device__ __forceinline__ unsigned long long pack2(float x)
{
    unsigned long long r;
    asm("mov.b64 %0, {%1, %1};" : "=l"(r) : "f"(x));
    return r;
}
__device__ __forceinline__ void fma2(unsigned long long& d, unsigned long long a, unsigned long long b)
{
    asm("fma.rn.f32x2 %0, %1, %2, %0;" : "+l"(d) : "l"(a), "l"(b));
}
__device__ __forceinline__ void unpack2(unsigned long long v, float& lo, float& hi)
{
    asm("mov.b64 {%0, %1}, %2;" : "=f"(lo), "=f"(hi) : "l"(v));
}

// ---------------- per-graph aggregation: h = in' + segsum(in'[row] -> col) ----------------
__global__ void agg_kernel(const float* __restrict__ in, float* __restrict__ outh,
                           const int* __restrict__ ei, int dimtot, int mode,
                           const float* __restrict__ scale, const float* __restrict__ shift,
                           const float* __restrict__ vemb)
{
    __shared__ float agg[NPG * 64];
    __shared__ int   se[2 * EPG];
    const int g  = blockIdx.x;
    const int d0 = blockIdx.y * 64;
    const int t  = threadIdx.x;

    for (int e = t; e < EPG; e += 64) {
        se[e]       = ei[g * EPG + e];
        se[EPG + e] = ei[EDGES + g * EPG + e];
    }
    for (int i = t; i < NPG * 64; i += 64) agg[i] = 0.f;
    __syncthreads();

    const int nb = g * NPG;
    const int d  = d0 + t;
    float sc_ = 0.f, sh_ = 0.f, ve = 0.f;
    if (mode) { sc_ = scale[d]; sh_ = shift[d]; ve = vemb[d]; }

    for (int e = 0; e < EPG; ++e) {
        const int r = se[e] - nb;
        const int c = se[EPG + e] - nb;
        float v = in[(size_t)(nb + r) * dimtot + d];
        if (mode) v = fmaxf(v * sc_ + sh_, 0.f) + ve;
        agg[c * 64 + t] += v;
    }
    __syncthreads();

    for (int n = 0; n < NPG; ++n) {
        float v = in[(size_t)(nb + n) * dimtot + d];
        if (mode) v = fmaxf(v * sc_ + sh_, 0.f) + ve;
        outh[(size_t)(nb + n) * dimtot + d] = v + agg[n * 64 + t];
    }
}

// ---------------- fp32 GEMM with packed f32x2 FMA + fused BN column stats ----------------
// C = A' @ B + bias, where A' = A or relu(A*tsc[k]+tsh[k]).
// Tiles: BM=128, BN=128, BK=16; 256 threads; 8x8 per-thread (accs paired along M).
// Also emits per-block column partials: part[by*512 + col] (+PART_SQ for squares).
#define BM  128
#define BNT 128
#define BK  16
__global__ __launch_bounds__(256)
void gemm_kernel(const float* __restrict__ A, const float* __restrict__ Bm,
                 const float* __restrict__ bias, float* __restrict__ C,
                 int K, int Nc,
                 const float* __restrict__ tsc, const float* __restrict__ tsh,
                 float* __restrict__ part)
{
    __shared__ float As[BK * BM];   // 2048 floats, transposed As[k][m]
    __shared__ float Bs[BK * BNT];  // 2048 floats
    const int tid = threadIdx.x;
    const int tx  = tid & 15;   // N dir (8 cols each)
    const int ty  = tid >> 4;   // M dir (8 rows each)
    const int n0  = blockIdx.x * BNT;
    const int m0  = blockIdx.y * BM;

    unsigned long long acc2[4][8];  // [m-pair][col]: lanes = rows (2im, 2im+1)
#pragma unroll
    for (int i = 0; i < 4; i++)
#pragma unroll
        for (int j = 0; j < 8; j++) acc2[i][j] = 0ull;

    for (int k0 = 0; k0 < K; k0 += BK) {
        // A tile (128x16) -> As[k][m]
#pragma unroll
        for (int i = 0; i < 2; ++i) {
            const int idx = tid * 2 + i;       // 0..511
            const int m   = idx >> 2;          // 0..127
            const int kq  = (idx & 3) * 4;     // 0,4,8,12
            float4 a = *(const float4*)(A + (size_t)(m0 + m) * K + k0 + kq);
            if (tsc) {
                const int kk = k0 + kq;
                a.x = fmaxf(a.x * tsc[kk + 0] + tsh[kk + 0], 0.f);
                a.y = fmaxf(a.y * tsc[kk + 1] + tsh[kk + 1], 0.f);
                a.z = fmaxf(a.z * tsc[kk + 2] + tsh[kk + 2], 0.f);
                a.w = fmaxf(a.w * tsc[kk + 3] + tsh[kk + 3], 0.f);
            }
            As[(kq + 0) * BM + m] = a.x;
            As[(kq + 1) * BM + m] = a.y;
            As[(kq + 2) * BM + m] = a.z;
            As[(kq + 3) * BM + m] = a.w;
        }
        // B tile (16x128): row k = tid>>4, 8 cols at (tid&15)*8
        {
            const int k  = tid >> 4;
            const int nq = (tid & 15) * 8;
            *(float4*)(Bs + k * BNT + nq) =
                *(const float4*)(Bm + (size_t)(k0 + k) * Nc + n0 + nq);
            *(float4*)(Bs + k * BNT + nq + 4) =
                *(const float4*)(Bm + (size_t)(k0 + k) * Nc + n0 + nq + 4);
        }
        __syncthreads();

#pragma unroll
        for (int kk = 0; kk < BK; ++kk) {
            // a: 8 consecutive rows -> 4 packed pairs, straight from SMEM
            ulonglong2 a01 = *(const ulonglong2*)(As + kk * BM + ty * 8);
            ulonglong2 a23 = *(const ulonglong2*)(As + kk * BM + ty * 8 + 4);
            unsigned long long av[4] = { a01.x, a01.y, a23.x, a23.y };
            float4 bq0 = *(const float4*)(Bs + kk * BNT + tx * 8);
            float4 bq1 = *(const float4*)(Bs + kk * BNT + tx * 8 + 4);
            unsigned long long bd[8];
            bd[0] = pack2(bq0.x); bd[1] = pack2(bq0.y);
            bd[2] = pack2(bq0.z); bd[3] = pack2(bq0.w);
            bd[4] = pack2(bq1.x); bd[5] = pack2(bq1.y);
            bd[6] = pack2(bq1.z); bd[7] = pack2(bq1.w);
#pragma unroll
            for (int i = 0; i < 4; i++)
#pragma unroll
                for (int j = 0; j < 8; j++)
                    fma2(acc2[i][j], av[i], bd[j]);
        }
        __syncthreads();
    }

    // Epilogue: bias add, store C, accumulate column stats
    float bb[8];
#pragma unroll
    for (int j = 0; j < 4; j++) bb[j]     = bias[n0 + tx * 8 + j];
#pragma unroll
    for (int j = 0; j < 4; j++) bb[4 + j] = bias[n0 + tx * 8 + 4 + j];

    float csum[8], csq[8];
#pragma unroll
    for (int j = 0; j < 8; j++) { csum[j] = 0.f; csq[j] = 0.f; }

#pragma unroll
    for (int im = 0; im < 4; ++im) {
        float r0[8], r1[8];
#pragma unroll
        for (int j = 0; j < 8; j++) {
            float lo, hi;
            unpack2(acc2[im][j], lo, hi);
            lo += bb[j]; hi += bb[j];
            r0[j] = lo; r1[j] = hi;
            csum[j] += lo + hi;
            csq[j]  += lo * lo + hi * hi;
        }
        const int mr0 = m0 + ty * 8 + 2 * im;
        *(float4*)(C + (size_t)mr0 * Nc + n0 + tx * 8)           = make_float4(r0[0], r0[1], r0[2], r0[3]);
        *(float4*)(C + (size_t)mr0 * Nc + n0 + tx * 8 + 4)       = make_float4(r0[4], r0[5], r0[6], r0[7]);
        *(float4*)(C + (size_t)(mr0 + 1) * Nc + n0 + tx * 8)     = make_float4(r1[0], r1[1], r1[2], r1[3]);
        *(float4*)(C + (size_t)(mr0 + 1) * Nc + n0 + tx * 8 + 4) = make_float4(r1[4], r1[5], r1[6], r1[7]);
    }

    // Deterministic in-block column reduction (reuse As for sums, Bs for sqs)
    __syncthreads();
#pragma unroll
    for (int j = 0; j < 8; j++) {
        As[ty * 128 + tx * 8 + j] = csum[j];
        Bs[ty * 128 + tx * 8 + j] = csq[j];
    }
    __syncthreads();
    if (tid < 128) {
        float s = 0.f, ss = 0.f;
#pragma unroll
        for (int b = 0; b < 16; ++b) {
            s  += As[b * 128 + tid];
            ss += Bs[b * 128 + tid];
        }
        part[blockIdx.y * 512 + n0 + tid]           = s;
        part[PART_SQ + blockIdx.y * 512 + n0 + tid] = ss;
    }
}

// ---------------- BN finalize: one block per channel, tree-reduce 256 partials ----------------
__global__ void finalize_kernel(const float* __restrict__ gg, const float* __restrict__ be,
                                const float* __restrict__ part,
                                float* __restrict__ scale, float* __restrict__ shift)
{
    __shared__ float ssum[256], ssq[256];
    const int c = blockIdx.x;
    const int t = threadIdx.x;
    ssum[t] = part[t * 512 + c];
    ssq[t]  = part[PART_SQ + t * 512 + c];
    __syncthreads();
#pragma unroll
    for (int o = 128; o; o >>= 1) {
        if (t < o) { ssum[t] += ssum[t + o]; ssq[t] += ssq[t + o]; }
        __syncthreads();
    }
    if (t == 0) {
        const float mu  = ssum[0] / (float)NNODES;
        const float var = ssq[0] / (float)NNODES - mu * mu;
        const float rs  = rsqrtf(var + BN_EPS);
        const float sc  = gg[c] * rs;
        scale[c] = sc;
        shift[c] = be[c] - mu * sc;
    }
}

// ---------------- per-node edge-logit halves ----------------
__global__ void nodedot_kernel(const float* __restrict__ Xn, const float* __restrict__ Wl,
                               const float* __restrict__ scale, const float* __restrict__ shift,
                               float* __restrict__ sa_o, float* __restrict__ sc_o)
{
    const int w = threadIdx.x >> 5;
    const int l = threadIdx.x & 31;
    const int n = blockIdx.x * 8 + w;
    float sa = 0.f, sc = 0.f;
#pragma unroll
    for (int i = 0; i < 8; ++i) {
        const int d = l + i * 32;
        const float v = Xn[(size_t)n * DD + d] * scale[d] + shift[d];
        sa = fmaf(v, Wl[d], sa);
        sc = fmaf(v, Wl[DD + d], sc);
    }
#pragma unroll
    for (int o = 16; o; o >>= 1) {
        sa += __shfl_down_sync(0xffffffffu, sa, o);
        sc += __shfl_down_sync(0xffffffffu, sc, o);
    }
    if (l == 0) { sa_o[n] = sa; sc_o[n] = sc; }
}

// ---------------- per-edge prediction ----------------
__global__ void pred_kernel(const int* __restrict__ ei, const float* __restrict__ bl,
                            const float* __restrict__ sa, const float* __restrict__ sc,
                            float* __restrict__ out)
{
    const int e = blockIdx.x * 256 + threadIdx.x;
    out[OFF_PRED + e] = sa[ei[e]] + sc[ei[EDGES + e]] + bl[0];
}

// ---------------- per-graph stable descending sort + output scatter ----------------
__device__ __forceinline__ unsigned ordered_f32(float f)
{
    unsigned u = __float_as_uint(f);
    return (u & 0x80000000u) ? ~u : (u | 0x80000000u);
}

__global__ void sort_kernel(const int* __restrict__ ei, float* __restrict__ out)
{
    __shared__ unsigned long long keys[EPG];
    const int g = blockIdx.x;
    const int t = threadIdx.x;
    const float* pred = out + OFF_PRED + (size_t)g * EPG;

    for (int j = t; j < EPG; j += 256) {
        const unsigned u = ordered_f32(pred[j]);
        keys[j] = ((unsigned long long)(~u) << 32) | (unsigned)j;
    }
    __syncthreads();

    for (int k = 2; k <= EPG; k <<= 1) {
        for (int j = k >> 1; j > 0; j >>= 1) {
            for (int i = t; i < EPG; i += 256) {
                const int ixj = i ^ j;
                if (ixj > i) {
                    const bool up = ((i & k) == 0);
                    unsigned long long a = keys[i], b = keys[ixj];
                    if ((a > b) == up) { keys[i] = b; keys[ixj] = a; }
                }
            }
            __syncthreads();
        }
    }

    for (int j = t; j < EPG; j += 256) {
        const int   idx = (int)(keys[j] & 0xffffffffu);
        const float p   = pred[idx];
        const int   s   = ei[g * EPG + idx];
        const int   dst = ei[EDGES + g * EPG + idx];
        if (j < NRES) {
            const int o = g * NRES + j;
            out[OFF_CEI + o]         = (float)s;
            out[OFF_CEI + 65536 + o] = (float)dst;
            out[OFF_CW + o]          = p;
        } else {
            const int o = g * NRES + (j - NRES);
            out[OFF_DEI + o]         = (float)s;
            out[OFF_DEI + 65536 + o] = (float)dst;
            out[OFF_DW + o]          = -p;
        }
    }
}

// ---------------- launch ----------------
extern "C" void kernel_launch(void* const* d_in, const int* in_sizes, int n_in,
                              void* d_out, int out_size)
{
    const float* x    = (const float*)d_in[0];
    const int*   ei   = (const int*)  d_in[1];
    const float* vemb = (const float*)d_in[3];
    const float* W1a  = (const float*)d_in[4];
    const float* b1a  = (const float*)d_in[5];
    const float* g1a  = (const float*)d_in[6];
    const float* be1a = (const float*)d_in[7];
    const float* W1b  = (const float*)d_in[8];
    const float* b1b  = (const float*)d_in[9];
    const float* g1   = (const float*)d_in[10];
    const float* be1  = (const float*)d_in[11];
    const float* W2a  = (const float*)d_in[12];
    const float* b2a  = (const float*)d_in[13];
    const float* g2a  = (const float*)d_in[14];
    const float* be2a = (const float*)d_in[15];
    const float* W2b  = (const float*)d_in[16];
    const float* b2b  = (const float*)d_in[17];
    const float* g2   = (const float*)d_in[18];
    const float* be2  = (const float*)d_in[19];
    const float* Wl   = (const float*)d_in[20];
    const float* bl   = (const float*)d_in[21];
    float* out = (float*)d_out;

    float *ph1, *pz, *po1, *ph2, *ppart, *pscale, *pshift, *psa, *psc;
    cudaGetSymbolAddress((void**)&ph1,    g_h1);
    cudaGetSymbolAddress((void**)&pz,     g_z);
    cudaGetSymbolAddress((void**)&po1,    g_o1);
    cudaGetSymbolAddress((void**)&ph2,    g_h2);
    cudaGetSymbolAddress((void**)&ppart,  g_part);
    cudaGetSymbolAddress((void**)&pscale, g_scale);
    cudaGetSymbolAddress((void**)&pshift, g_shift);
    cudaGetSymbolAddress((void**)&psa,    g_sa);
    cudaGetSymbolAddress((void**)&psc,    g_sc);

    // Layer 1
    agg_kernel<<<dim3(BGR, DIN / 64), 64>>>(x, ph1, ei, DIN, 0, nullptr, nullptr, nullptr);
    gemm_kernel<<<dim3(D2 / BNT, NNODES / BM), 256>>>(ph1, W1a, b1a, pz, DIN, D2, nullptr, nullptr, ppart);
    finalize_kernel<<<512, 256>>>(g1a, be1a, ppart, pscale, pshift);
    gemm_kernel<<<dim3(DD / BNT, NNODES / BM), 256>>>(pz, W1b, b1b, po1, D2, DD, pscale, pshift, ppart);
    finalize_kernel<<<256, 256>>>(g1, be1, ppart, pscale, pshift);

    // Layer 2 (post = relu(bn(o1)) + vemb fused into aggregation)
    agg_kernel<<<dim3(BGR, DD / 64), 64>>>(po1, ph2, ei, DD, 1, pscale, pshift, vemb);
    gemm_kernel<<<dim3(D2 / BNT, NNODES / BM), 256>>>(ph2, W2a, b2a, pz, DD, D2, nullptr, nullptr, ppart);
    finalize_kernel<<<512, 256>>>(g2a, be2a, ppart, pscale, pshift);
    gemm_kernel<<<dim3(DD / BNT, NNODES / BM), 256>>>(pz, W2b, b2b, po1, D2, DD, pscale, pshift, ppart);
    finalize_kernel<<<256, 256>>>(g2, be2, ppart, pscale, pshift);

    // Edge scores + per-graph stable top-k split
    nodedot_kernel<<<NNODES / 8, 256>>>(po1, Wl, pscale, pshift, psa, psc);
    pred_kernel<<<EDGES / 256, 256>>>(ei, bl, psa, psc, out);
    sort_kernel<<<BGR, 256>>>(ei, out);
}

// round 4
// speedup vs baseline: 1.4373x; 1.4373x over previous
#include <cuda_runtime.h>
#include <cuda_bf16.h>
#include <math.h>
#include <stdint.h>

// Problem constants
#define NNODES 32768
#define DIN    128
#define DD     256
#define D2     512
#define EDGES  131072
#define BGR    256
#define EPG    512
#define NPG    128
#define NRES   256
#define BN_EPS 1e-5f

// Output layout (float32, 524288 elems)
#define OFF_CEI   0
#define OFF_CW    131072
#define OFF_DEI   196608
#define OFF_DW    327680
#define OFF_PRED  393216

// ---------------- scratch (device globals; no allocation) ----------------
__device__ __align__(16) float g_z [NNODES * D2];      // fp32 GEMM out (z1/z2)
__device__ __align__(16) float g_o1[NNODES * DD];      // fp32 GEMM out (o1, then xn)
__device__ __align__(16) float g_part[2 * 256 * 512];
#define PART_SQ (256 * 512)
__device__ float g_scale[512];
__device__ float g_shift[512];
__device__ float g_sa[NNODES];
__device__ float g_sc[NNODES];
// bf16 hi/lo operand buffers
__device__ __align__(16) __nv_bfloat16 g_h1h[NNODES * DIN], g_h1l[NNODES * DIN];
__device__ __align__(16) __nv_bfloat16 g_zh [NNODES * D2],  g_zl [NNODES * D2];
__device__ __align__(16) __nv_bfloat16 g_h2h[NNODES * DD],  g_h2l[NNODES * DD];
__device__ __align__(16) __nv_bfloat16 g_w1h[D2 * DIN], g_w1l[D2 * DIN];
__device__ __align__(16) __nv_bfloat16 g_w2h[DD * D2],  g_w2l[DD * D2];
__device__ __align__(16) __nv_bfloat16 g_w3h[D2 * DD],  g_w3l[D2 * DD];
__device__ __align__(16) __nv_bfloat16 g_w4h[DD * D2],  g_w4l[DD * D2];

// ---------------- helpers ----------------
__device__ __forceinline__ void bsplit(float v, __nv_bfloat16& h, __nv_bfloat16& l)
{
    h = __float2bfloat16(v);
    l = __float2bfloat16(v - __bfloat162float(h));
}

__device__ __forceinline__ void mma_bf16(float* c, const uint32_t* a, const uint32_t* b)
{
    asm volatile("mma.sync.aligned.m16n8k16.row.col.f32.bf16.bf16.f32 "
                 "{%0,%1,%2,%3}, {%4,%5,%6,%7}, {%8,%9}, {%0,%1,%2,%3};"
                 : "+f"(c[0]), "+f"(c[1]), "+f"(c[2]), "+f"(c[3])
                 : "r"(a[0]), "r"(a[1]), "r"(a[2]), "r"(a[3]), "r"(b[0]), "r"(b[1]));
}

#define CP16(dst, src) \
    asm volatile("cp.async.cg.shared.global [%0], [%1], 16;" :: "r"(dst), "l"(src) : "memory")

// ---------------- bf16x3 GEMM: C[M,Nc] = (Ah+Al)[M,K] @ (Bh+Bl)[Nc,K]^T + bias ----------------
// CTA tile 128x256, BK=32, 256 threads = 8 warps (2m x 4n), warp tile 64x64.
// Rows padded to 40 bf16 (80B) -> conflict-free fragment LDS. Fused BN column stats.
#define LDS_ROW 40
#define A_SZ (128 * LDS_ROW)
#define B_SZ (256 * LDS_ROW)
#define BUFU (2 * A_SZ + 2 * B_SZ)          // bf16 units per buffer (30720)
#define GEMM_SMEM (2 * BUFU * 2)            // bytes (122880)

__global__ __launch_bounds__(256, 1)
void gemm_bf16_kernel(const __nv_bfloat16* __restrict__ Ah, const __nv_bfloat16* __restrict__ Al,
                      const __nv_bfloat16* __restrict__ Bh, const __nv_bfloat16* __restrict__ Bl,
                      const float* __restrict__ bias, float* __restrict__ C,
                      int K, int Nc, float* __restrict__ part)
{
    extern __shared__ __align__(16) __nv_bfloat16 smem[];
    const int tid  = threadIdx.x;
    const int lane = tid & 31;
    const int wid  = tid >> 5;
    const int gid  = lane >> 2, tig = lane & 3;
    const int wm   = (wid >> 2) * 64;   // 2 m-warps
    const int wn   = (wid & 3) * 64;    // 4 n-warps
    const int n0   = blockIdx.x * 256;
    const int m0   = blockIdx.y * 128;
    const int NK   = K >> 5;
    const uint32_t sbase = (uint32_t)__cvta_generic_to_shared(smem);

    float acc[4][8][4];
#pragma unroll
    for (int mt = 0; mt < 4; ++mt)
#pragma unroll
        for (int nt = 0; nt < 8; ++nt)
#pragma unroll
            for (int j = 0; j < 4; ++j) acc[mt][nt][j] = 0.f;

#define ISSUE(IT, B) do {                                                          \
    const int koff = (IT) * 32;                                                    \
    for (int c = tid; c < 3072; c += 256) {                                        \
        const __nv_bfloat16* src; uint32_t doff;                                   \
        if (c < 1024) {                                                            \
            const int row = (c & 511) >> 2, q = c & 3;                             \
            src = (c < 512 ? Ah : Al) + (size_t)(m0 + row) * K + koff + q * 8;     \
            doff = (uint32_t)((B) * BUFU + (c < 512 ? 0 : A_SZ) + row * LDS_ROW + q * 8); \
        } else {                                                                   \
            const int cc = c - 1024;                                               \
            const int row = (cc & 1023) >> 2, q = cc & 3;                          \
            src = (cc < 1024 ? Bh : Bl) + (size_t)(n0 + row) * K + koff + q * 8;   \
            doff = (uint32_t)((B) * BUFU + 2 * A_SZ + (cc < 1024 ? 0 : B_SZ) + row * LDS_ROW + q * 8); \
        }                                                                          \
        CP16(sbase + doff * 2, src);                                               \
    }                                                                              \
    asm volatile("cp.async.commit_group;" ::: "memory");                           \
} while (0)

    ISSUE(0, 0);

    for (int it = 0; it < NK; ++it) {
        const int cur = it & 1;
        if (it + 1 < NK) {
            ISSUE(it + 1, 1 - cur);
            asm volatile("cp.async.wait_group 1;" ::: "memory");
        } else {
            asm volatile("cp.async.wait_group 0;" ::: "memory");
        }
        __syncthreads();

        const __nv_bfloat16* sAh = smem + cur * BUFU;
        const __nv_bfloat16* sAl = sAh + A_SZ;
        const __nv_bfloat16* sBh = sAh + 2 * A_SZ;
        const __nv_bfloat16* sBl = sBh + B_SZ;
#pragma unroll
        for (int ks = 0; ks < 2; ++ks) {
            const int ka = ks * 16 + 2 * tig;
            uint32_t ah[4][4], ao[4][4], bb[8][2];
#pragma unroll
            for (int mt = 0; mt < 4; ++mt) {
                const __nv_bfloat16* p = sAh + (wm + mt * 16 + gid) * LDS_ROW + ka;
                ah[mt][0] = *(const uint32_t*)p;
                ah[mt][1] = *(const uint32_t*)(p + 8 * LDS_ROW);
                ah[mt][2] = *(const uint32_t*)(p + 8);
                ah[mt][3] = *(const uint32_t*)(p + 8 * LDS_ROW + 8);
            }
#pragma unroll
            for (int nt = 0; nt < 8; ++nt) {
                const __nv_bfloat16* p = sBh + (wn + nt * 8 + gid) * LDS_ROW + ka;
                bb[nt][0] = *(const uint32_t*)p;
                bb[nt][1] = *(const uint32_t*)(p + 8);
            }
            // pass 1: Ahi * Bhi
#pragma unroll
            for (int mt = 0; mt < 4; ++mt)
#pragma unroll
                for (int nt = 0; nt < 8; ++nt)
                    mma_bf16(acc[mt][nt], ah[mt], bb[nt]);
            // pass 2: Alo * Bhi
#pragma unroll
            for (int mt = 0; mt < 4; ++mt) {
                const __nv_bfloat16* p = sAl + (wm + mt * 16 + gid) * LDS_ROW + ka;
                ao[mt][0] = *(const uint32_t*)p;
                ao[mt][1] = *(const uint32_t*)(p + 8 * LDS_ROW);
                ao[mt][2] = *(const uint32_t*)(p + 8);
                ao[mt][3] = *(const uint32_t*)(p + 8 * LDS_ROW + 8);
            }
#pragma unroll
            for (int mt = 0; mt < 4; ++mt)
#pragma unroll
                for (int nt = 0; nt < 8; ++nt)
                    mma_bf16(acc[mt][nt], ao[mt], bb[nt]);
            // pass 3: Ahi * Blo
#pragma unroll
            for (int nt = 0; nt < 8; ++nt) {
                const __nv_bfloat16* p = sBl + (wn + nt * 8 + gid) * LDS_ROW + ka;
                bb[nt][0] = *(const uint32_t*)p;
                bb[nt][1] = *(const uint32_t*)(p + 8);
            }
#pragma unroll
            for (int mt = 0; mt < 4; ++mt)
#pragma unroll
                for (int nt = 0; nt < 8; ++nt)
                    mma_bf16(acc[mt][nt], ah[mt], bb[nt]);
        }
        __syncthreads();
    }

    // Epilogue: bias, store C, fused deterministic column stats
    float colsum[16], colsq[16];
#pragma unroll
    for (int i = 0; i < 16; ++i) { colsum[i] = 0.f; colsq[i] = 0.f; }

#pragma unroll
    for (int mt = 0; mt < 4; ++mt)
#pragma unroll
        for (int nt = 0; nt < 8; ++nt) {
            const int r   = m0 + wm + mt * 16 + gid;
            const int col = n0 + wn + nt * 8 + 2 * tig;
            const float b0 = bias[col], b1 = bias[col + 1];
            const float v00 = acc[mt][nt][0] + b0, v01 = acc[mt][nt][1] + b1;
            const float v10 = acc[mt][nt][2] + b0, v11 = acc[mt][nt][3] + b1;
            *(float2*)(C + (size_t)r * Nc + col)       = make_float2(v00, v01);
            *(float2*)(C + (size_t)(r + 8) * Nc + col) = make_float2(v10, v11);
            colsum[nt * 2 + 0] += v00 + v10;  colsq[nt * 2 + 0] += v00 * v00 + v10 * v10;
            colsum[nt * 2 + 1] += v01 + v11;  colsq[nt * 2 + 1] += v01 * v01 + v11 * v11;
        }
#pragma unroll
    for (int i = 0; i < 16; ++i) {
#pragma unroll
        for (int off = 16; off >= 4; off >>= 1) {
            colsum[i] += __shfl_down_sync(0xffffffffu, colsum[i], off);
            colsq[i]  += __shfl_down_sync(0xffffffffu, colsq[i],  off);
        }
    }
    __syncthreads();   // smem buffers no longer needed
    float* ssum = (float*)smem;        // [2][256]
    float* ssq  = ssum + 512;
    if (gid == 0) {
        const int mwarp = wid >> 2;
#pragma unroll
        for (int nt = 0; nt < 8; ++nt) {
            const int c = wn + nt * 8 + 2 * tig;
            ssum[mwarp * 256 + c]     = colsum[nt * 2 + 0];
            ssum[mwarp * 256 + c + 1] = colsum[nt * 2 + 1];
            ssq [mwarp * 256 + c]     = colsq[nt * 2 + 0];
            ssq [mwarp * 256 + c + 1] = colsq[nt * 2 + 1];
        }
    }
    __syncthreads();
    if (tid < 256) {
        part[blockIdx.y * 512 + n0 + tid]           = ssum[tid] + ssum[256 + tid];
        part[PART_SQ + blockIdx.y * 512 + n0 + tid] = ssq[tid]  + ssq[256 + tid];
    }
}

// ---------------- weight transpose + bf16 split: W[k][n] -> Wh/Wl[n][k] ----------------
__global__ void wsplit_kernel(const float* __restrict__ W, __nv_bfloat16* __restrict__ Wh,
                              __nv_bfloat16* __restrict__ Wl, int K, int N)
{
    __shared__ float tile[32][33];
    const int n0 = blockIdx.x * 32, k0 = blockIdx.y * 32;
    for (int i = threadIdx.y; i < 32; i += 8)
        tile[i][threadIdx.x] = W[(size_t)(k0 + i) * N + n0 + threadIdx.x];
    __syncthreads();
    for (int i = threadIdx.y; i < 32; i += 8) {
        const float v = tile[threadIdx.x][i];
        __nv_bfloat16 h, l;
        bsplit(v, h, l);
        Wh[(size_t)(n0 + i) * K + k0 + threadIdx.x] = h;
        Wl[(size_t)(n0 + i) * K + k0 + threadIdx.x] = l;
    }
}

// ---------------- z transform + bf16 split: relu(z*scale[k]+shift[k]) -> hi/lo ----------------
__global__ void zsplit_kernel(const float* __restrict__ z, const float* __restrict__ scale,
                              const float* __restrict__ shift,
                              __nv_bfloat16* __restrict__ zh, __nv_bfloat16* __restrict__ zl)
{
    const size_t i = ((size_t)blockIdx.x * 256 + threadIdx.x) * 4;
    const int k = (int)(i & (D2 - 1));
    float4 v = *(const float4*)(z + i);
    v.x = fmaxf(v.x * scale[k + 0] + shift[k + 0], 0.f);
    v.y = fmaxf(v.y * scale[k + 1] + shift[k + 1], 0.f);
    v.z = fmaxf(v.z * scale[k + 2] + shift[k + 2], 0.f);
    v.w = fmaxf(v.w * scale[k + 3] + shift[k + 3], 0.f);
    __nv_bfloat16 h0, h1, h2, h3, l0, l1, l2, l3;
    bsplit(v.x, h0, l0); bsplit(v.y, h1, l1); bsplit(v.z, h2, l2); bsplit(v.w, h3, l3);
    *(__nv_bfloat162*)(zh + i)     = __nv_bfloat162(h0, h1);
    *(__nv_bfloat162*)(zh + i + 2) = __nv_bfloat162(h2, h3);
    *(__nv_bfloat162*)(zl + i)     = __nv_bfloat162(l0, l1);
    *(__nv_bfloat162*)(zl + i + 2) = __nv_bfloat162(l2, l3);
}

// ---------------- per-graph aggregation, bf16 hi/lo output ----------------
__global__ void agg_kernel(const float* __restrict__ in, __nv_bfloat16* __restrict__ oh,
                           __nv_bfloat16* __restrict__ ol,
                           const int* __restrict__ ei, int dimtot, int mode,
                           const float* __restrict__ scale, const float* __restrict__ shift,
                           const float* __restrict__ vemb)
{
    __shared__ float agg[NPG * 64];
    __shared__ int   se[2 * EPG];
    const int g  = blockIdx.x;
    const int d0 = blockIdx.y * 64;
    const int t  = threadIdx.x;

    for (int e = t; e < EPG; e += 64) {
        se[e]       = ei[g * EPG + e];
        se[EPG + e] = ei[EDGES + g * EPG + e];
    }
    for (int i = t; i < NPG * 64; i += 64) agg[i] = 0.f;
    __syncthreads();

    const int nb = g * NPG;
    const int d  = d0 + t;
    float sc_ = 0.f, sh_ = 0.f, ve = 0.f;
    if (mode) { sc_ = scale[d]; sh_ = shift[d]; ve = vemb[d]; }

    for (int e = 0; e < EPG; ++e) {
        const int r = se[e] - nb;
        const int c = se[EPG + e] - nb;
        float v = in[(size_t)(nb + r) * dimtot + d];
        if (mode) v = fmaxf(v * sc_ + sh_, 0.f) + ve;
        agg[c * 64 + t] += v;
    }
    __syncthreads();

    for (int n = 0; n < NPG; ++n) {
        float v = in[(size_t)(nb + n) * dimtot + d];
        if (mode) v = fmaxf(v * sc_ + sh_, 0.f) + ve;
        const float h = v + agg[n * 64 + t];
        __nv_bfloat16 hh, ll;
        bsplit(h, hh, ll);
        oh[(size_t)(nb + n) * dimtot + d] = hh;
        ol[(size_t)(nb + n) * dimtot + d] = ll;
    }
}

// ---------------- BN finalize ----------------
__global__ void finalize_kernel(const float* __restrict__ gg, const float* __restrict__ be,
                                const float* __restrict__ part,
                                float* __restrict__ scale, float* __restrict__ shift)
{
    __shared__ float ssum[256], ssq[256];
    const int c = blockIdx.x;
    const int t = threadIdx.x;
    ssum[t] = part[t * 512 + c];
    ssq[t]  = part[PART_SQ + t * 512 + c];
    __syncthreads();
#pragma unroll
    for (int o = 128; o; o >>= 1) {
        if (t < o) { ssum[t] += ssum[t + o]; ssq[t] += ssq[t + o]; }
        __syncthreads();
    }
    if (t == 0) {
        const float mu  = ssum[0] / (float)NNODES;
        const float var = ssq[0] / (float)NNODES - mu * mu;
        const float rs  = rsqrtf(var + BN_EPS);
        const float sc  = gg[c] * rs;
        scale[c] = sc;
        shift[c] = be[c] - mu * sc;
    }
}

// ---------------- per-node edge-logit halves ----------------
__global__ void nodedot_kernel(const float* __restrict__ Xn, const float* __restrict__ Wl,
                               const float* __restrict__ scale, const float* __restrict__ shift,
                               float* __restrict__ sa_o, float* __restrict__ sc_o)
{
    const int w = threadIdx.x >> 5;
    const int l = threadIdx.x & 31;
    const int n = blockIdx.x * 8 + w;
    float sa = 0.f, sc = 0.f;
#pragma unroll
    for (int i = 0; i < 8; ++i) {
        const int d = l + i * 32;
        const float v = Xn[(size_t)n * DD + d] * scale[d] + shift[d];
        sa = fmaf(v, Wl[d], sa);
        sc = fmaf(v, Wl[DD + d], sc);
    }
#pragma unroll
    for (int o = 16; o; o >>= 1) {
        sa += __shfl_down_sync(0xffffffffu, sa, o);
        sc += __shfl_down_sync(0xffffffffu, sc, o);
    }
    if (l == 0) { sa_o[n] = sa; sc_o[n] = sc; }
}

// ---------------- per-edge prediction ----------------
__global__ void pred_kernel(const int* __restrict__ ei, const float* __restrict__ bl,
                            const float* __restrict__ sa, const float* __restrict__ sc,
                            float* __restrict__ out)
{
    const int e = blockIdx.x * 256 + threadIdx.x;
    out[OFF_PRED + e] = sa[ei[e]] + sc[ei[EDGES + e]] + bl[0];
}

// ---------------- per-graph stable descending sort + output scatter ----------------
__device__ __forceinline__ unsigned ordered_f32(float f)
{
    unsigned u = __float_as_uint(f);
    return (u & 0x80000000u) ? ~u : (u | 0x80000000u);
}

__global__ void sort_kernel(const int* __restrict__ ei, float* __restrict__ out)
{
    __shared__ unsigned long long keys[EPG];
    const int g = blockIdx.x;
    const int t = threadIdx.x;
    const float* pred = out + OFF_PRED + (size_t)g * EPG;

    for (int j = t; j < EPG; j += 256) {
        const unsigned u = ordered_f32(pred[j]);
        keys[j] = ((unsigned long long)(~u) << 32) | (unsigned)j;
    }
    __syncthreads();

    for (int k = 2; k <= EPG; k <<= 1) {
        for (int j = k >> 1; j > 0; j >>= 1) {
            for (int i = t; i < EPG; i += 256) {
                const int ixj = i ^ j;
                if (ixj > i) {
                    const bool up = ((i & k) == 0);
                    unsigned long long a = keys[i], b = keys[ixj];
                    if ((a > b) == up) { keys[i] = b; keys[ixj] = a; }
                }
            }
            __syncthreads();
        }
    }

    for (int j = t; j < EPG; j += 256) {
        const int   idx = (int)(keys[j] & 0xffffffffu);
        const float p   = pred[idx];
        const int   s   = ei[g * EPG + idx];
        const int   dst = ei[EDGES + g * EPG + idx];
        if (j < NRES) {
            const int o = g * NRES + j;
            out[OFF_CEI + o]         = (float)s;
            out[OFF_CEI + 65536 + o] = (float)dst;
            out[OFF_CW + o]          = p;
        } else {
            const int o = g * NRES + (j - NRES);
            out[OFF_DEI + o]         = (float)s;
            out[OFF_DEI + 65536 + o] = (float)dst;
            out[OFF_DW + o]          = -p;
        }
    }
}

// ---------------- launch ----------------
extern "C" void kernel_launch(void* const* d_in, const int* in_sizes, int n_in,
                              void* d_out, int out_size)
{
    const float* x    = (const float*)d_in[0];
    const int*   ei   = (const int*)  d_in[1];
    const float* vemb = (const float*)d_in[3];
    const float* W1a  = (const float*)d_in[4];
    const float* b1a  = (const float*)d_in[5];
    const float* g1a  = (const float*)d_in[6];
    const float* be1a = (const float*)d_in[7];
    const float* W1b  = (const float*)d_in[8];
    const float* b1b  = (const float*)d_in[9];
    const float* g1   = (const float*)d_in[10];
    const float* be1  = (const float*)d_in[11];
    const float* W2a  = (const float*)d_in[12];
    const float* b2a  = (const float*)d_in[13];
    const float* g2a  = (const float*)d_in[14];
    const float* be2a = (const float*)d_in[15];
    const float* W2b  = (const float*)d_in[16];
    const float* b2b  = (const float*)d_in[17];
    const float* g2   = (const float*)d_in[18];
    const float* be2  = (const float*)d_in[19];
    const float* Wl   = (const float*)d_in[20];
    const float* bl   = (const float*)d_in[21];
    float* out = (float*)d_out;

    float *pz, *po1, *ppart, *pscale, *pshift, *psa, *psc;
    __nv_bfloat16 *h1h, *h1l, *zh, *zl, *h2h, *h2l;
    __nv_bfloat16 *w1h, *w1l, *w2h, *w2l, *w3h, *w3l, *w4h, *w4l;
    cudaGetSymbolAddress((void**)&pz,     g_z);
    cudaGetSymbolAddress((void**)&po1,    g_o1);
    cudaGetSymbolAddress((void**)&ppart,  g_part);
    cudaGetSymbolAddress((void**)&pscale, g_scale);
    cudaGetSymbolAddress((void**)&pshift, g_shift);
    cudaGetSymbolAddress((void**)&psa,    g_sa);
    cudaGetSymbolAddress((void**)&psc,    g_sc);
    cudaGetSymbolAddress((void**)&h1h, g_h1h); cudaGetSymbolAddress((void**)&h1l, g_h1l);
    cudaGetSymbolAddress((void**)&zh,  g_zh);  cudaGetSymbolAddress((void**)&zl,  g_zl);
    cudaGetSymbolAddress((void**)&h2h, g_h2h); cudaGetSymbolAddress((void**)&h2l, g_h2l);
    cudaGetSymbolAddress((void**)&w1h, g_w1h); cudaGetSymbolAddress((void**)&w1l, g_w1l);
    cudaGetSymbolAddress((void**)&w2h, g_w2h); cudaGetSymbolAddress((void**)&w2l, g_w2l);
    cudaGetSymbolAddress((void**)&w3h, g_w3h); cudaGetSymbolAddress((void**)&w3l, g_w3l);
    cudaGetSymbolAddress((void**)&w4h, g_w4h); cudaGetSymbolAddress((void**)&w4l, g_w4l);

    cudaFuncSetAttribute(gemm_bf16_kernel, cudaFuncAttributeMaxDynamicSharedMemorySize, GEMM_SMEM);

    // weight transpose + split
    wsplit_kernel<<<dim3(512/32, 128/32), dim3(32, 8)>>>(W1a, w1h, w1l, 128, 512);
    wsplit_kernel<<<dim3(256/32, 512/32), dim3(32, 8)>>>(W1b, w2h, w2l, 512, 256);
    wsplit_kernel<<<dim3(512/32, 256/32), dim3(32, 8)>>>(W2a, w3h, w3l, 256, 512);
    wsplit_kernel<<<dim3(256/32, 512/32), dim3(32, 8)>>>(W2b, w4h, w4l, 512, 256);

    // Layer 1
    agg_kernel<<<dim3(BGR, DIN / 64), 64>>>(x, h1h, h1l, ei, DIN, 0, nullptr, nullptr, nullptr);
    gemm_bf16_kernel<<<dim3(2, 256), 256, GEMM_SMEM>>>(h1h, h1l, w1h, w1l, b1a, pz, 128, 512, ppart);
    finalize_kernel<<<512, 256>>>(g1a, be1a, ppart, pscale, pshift);
    zsplit_kernel<<<NNODES * D2 / 1024, 256>>>(pz, pscale, pshift, zh, zl);
    gemm_bf16_kernel<<<dim3(1, 256), 256, GEMM_SMEM>>>(zh, zl, w2h, w2l, b1b, po1, 512, 256, ppart);
    finalize_kernel<<<256, 256>>>(g1, be1, ppart, pscale, pshift);

    // Layer 2 (post = relu(bn(o1)) + vemb fused into aggregation)
    agg_kernel<<<dim3(BGR, DD / 64), 64>>>(po1, h2h, h2l, ei, DD, 1, pscale, pshift, vemb);
    gemm_bf16_kernel<<<dim3(2, 256), 256, GEMM_SMEM>>>(h2h, h2l, w3h, w3l, b2a, pz, 256, 512, ppart);
    finalize_kernel<<<512, 256>>>(g2a, be2a, ppart, pscale, pshift);
    zsplit_kernel<<<NNODES * D2 / 1024, 256>>>(pz, pscale, pshift, zh, zl);
    gemm_bf16_kernel<<<dim3(1, 256), 256, GEMM_SMEM>>>(zh, zl, w4h, w4l, b2b, po1, 512, 256, ppart);
    finalize_kernel<<<256, 256>>>(g2, be2, ppart, pscale, pshift);

    // Edge scores + per-graph stable top-k split
    nodedot_kernel<<<NNODES / 8, 256>>>(po1, Wl, pscale, pshift, psa, psc);
    pred_kernel<<<EDGES / 256, 256>>>(ei, bl, psa, psc, out);
    sort_kernel<<<BGR, 256>>>(ei, out);
}

// round 5
// speedup vs baseline: 1.5476x; 1.0767x over previous
#include <cuda_runtime.h>
#include <cuda_bf16.h>
#include <math.h>
#include <stdint.h>

// Problem constants
#define NNODES 32768
#define DIN    128
#define DD     256
#define D2     512
#define EDGES  131072
#define BGR    256
#define EPG    512
#define NPG    128
#define NRES   256
#define BN_EPS 1e-5f

// Output layout (float32, 524288 elems)
#define OFF_CEI   0
#define OFF_CW    131072
#define OFF_DEI   196608
#define OFF_DW    327680
#define OFF_PRED  393216

// ---------------- scratch (device globals; no allocation) ----------------
__device__ __align__(16) float g_z [NNODES * D2];      // fp32 GEMM out (z1/z2)
__device__ __align__(16) float g_o1[NNODES * DD];      // fp32 GEMM out (o1, then xn)
__device__ __align__(16) float g_part[2 * 256 * 512];
#define PART_SQ (256 * 512)
__device__ float g_scale[512];
__device__ float g_shift[512];
__device__ float g_sa[NNODES];
__device__ float g_sc[NNODES];
// bf16 hi/lo operand buffers
__device__ __align__(16) __nv_bfloat16 g_h1h[NNODES * DIN], g_h1l[NNODES * DIN];
__device__ __align__(16) __nv_bfloat16 g_h2h[NNODES * DD],  g_h2l[NNODES * DD];
__device__ __align__(16) __nv_bfloat16 g_w1h[D2 * DIN], g_w1l[D2 * DIN];
__device__ __align__(16) __nv_bfloat16 g_w2h[DD * D2],  g_w2l[DD * D2];
__device__ __align__(16) __nv_bfloat16 g_w3h[D2 * DD],  g_w3l[D2 * DD];
__device__ __align__(16) __nv_bfloat16 g_w4h[DD * D2],  g_w4l[DD * D2];

// ---------------- helpers ----------------
__device__ __forceinline__ void bsplit(float v, __nv_bfloat16& h, __nv_bfloat16& l)
{
    h = __float2bfloat16(v);
    l = __float2bfloat16(v - __bfloat162float(h));
}

__device__ __forceinline__ void mma_bf16(float* c, const uint32_t* a, const uint32_t* b)
{
    asm volatile("mma.sync.aligned.m16n8k16.row.col.f32.bf16.bf16.f32 "
                 "{%0,%1,%2,%3}, {%4,%5,%6,%7}, {%8,%9}, {%0,%1,%2,%3};"
                 : "+f"(c[0]), "+f"(c[1]), "+f"(c[2]), "+f"(c[3])
                 : "r"(a[0]), "r"(a[1]), "r"(a[2]), "r"(a[3]), "r"(b[0]), "r"(b[1]));
}

#define CP16(dst, src) \
    asm volatile("cp.async.cg.shared.global [%0], [%1], 16;" :: "r"(dst), "l"(src) : "memory")
#define LDM_X4(r0, r1, r2, r3, addr) \
    asm volatile("ldmatrix.sync.aligned.m8n8.x4.shared.b16 {%0,%1,%2,%3}, [%4];" \
                 : "=r"(r0), "=r"(r1), "=r"(r2), "=r"(r3) : "r"(addr))

// ---------------- bf16x3 GEMM: C[M,Nc] = (Ah+Al)[M,K] @ (Bh+Bl)[Nc,K]^T + bias ----------------
// CTA tile 128x256, BK=32, 256 threads = 8 warps (2m x 4n), warp tile 64x64.
// Rows padded to 40 bf16 (80B) -> conflict-free LDS/ldmatrix. Fused BN column stats.
// TR=true: A comes from fp32 Af with relu(a*scale+shift) transform + bf16 split in producer.
#define LDS_ROW 40
#define A_SZ (128 * LDS_ROW)
#define B_SZ (256 * LDS_ROW)
#define BUFU (2 * A_SZ + 2 * B_SZ)          // bf16 units per buffer (30720)
#define GEMM_SMEM (2 * BUFU * 2 + 4096)     // + scale/shift cache

template<bool TR>
__global__ __launch_bounds__(256, 1)
void gemm_bf16_kernel(const __nv_bfloat16* __restrict__ Ah, const __nv_bfloat16* __restrict__ Al,
                      const float* __restrict__ Af, const float* __restrict__ tsc,
                      const float* __restrict__ tsh,
                      const __nv_bfloat16* __restrict__ Bh, const __nv_bfloat16* __restrict__ Bl,
                      const float* __restrict__ bias, float* __restrict__ C,
                      int K, int Nc, float* __restrict__ part)
{
    extern __shared__ __align__(16) __nv_bfloat16 smem[];
    float* sScale = (float*)(smem + 2 * BUFU);
    float* sShift = sScale + 512;
    const int tid  = threadIdx.x;
    const int lane = tid & 31;
    const int wid  = tid >> 5;
    const int gid  = lane >> 2, tig = lane & 3;
    const int wm   = (wid >> 2) * 64;   // 2 m-warps
    const int wn   = (wid & 3) * 64;    // 4 n-warps
    const int n0   = blockIdx.x * 256;
    const int m0   = blockIdx.y * 128;
    const int NK   = K >> 5;
    const uint32_t sbase = (uint32_t)__cvta_generic_to_shared(smem);

    if (TR) {
        for (int i = tid; i < K; i += 256) { sScale[i] = tsc[i]; sShift[i] = tsh[i]; }
        __syncthreads();
    }

    // ldmatrix lane offsets (bytes)
    const uint32_t aoff = (uint32_t)(((wm + (lane & 15)) * LDS_ROW + ((lane >> 4) << 3)) * 2);
    const uint32_t boff = (uint32_t)(((wn + (lane & 7) + (((lane >> 4) & 1) << 3)) * LDS_ROW
                                      + (((lane >> 3) & 1) << 3)) * 2);

    float acc[4][8][4];
#pragma unroll
    for (int mt = 0; mt < 4; ++mt)
#pragma unroll
        for (int nt = 0; nt < 8; ++nt)
#pragma unroll
            for (int j = 0; j < 4; ++j) acc[mt][nt][j] = 0.f;

    // B producer via cp.async: 2048 16B-chunks (256 rows hi + 256 rows lo, 4 chunks/row)
#define ISSUE_B(IT, B) do {                                                        \
    const int koff = (IT) * 32;                                                    \
    for (int c = tid; c < 2048; c += 256) {                                        \
        const int row = (c & 1023) >> 2, q = c & 3;                                \
        const __nv_bfloat16* src = (c < 1024 ? Bh : Bl) + (size_t)(n0 + row) * K + koff + q * 8; \
        const uint32_t doff = (uint32_t)((B) * BUFU + 2 * A_SZ + (c < 1024 ? 0 : B_SZ) + row * LDS_ROW + q * 8); \
        CP16(sbase + doff * 2, src);                                               \
    }                                                                              \
    asm volatile("cp.async.commit_group;" ::: "memory");                           \
} while (0)

    // A+B producer via cp.async (bf16 A path)
#define ISSUE_AB(IT, B) do {                                                       \
    const int koff = (IT) * 32;                                                    \
    for (int c = tid; c < 1024; c += 256) {                                        \
        const int row = (c & 511) >> 2, q = c & 3;                                 \
        const __nv_bfloat16* src = (c < 512 ? Ah : Al) + (size_t)(m0 + row) * K + koff + q * 8; \
        const uint32_t doff = (uint32_t)((B) * BUFU + (c < 512 ? 0 : A_SZ) + row * LDS_ROW + q * 8); \
        CP16(sbase + doff * 2, src);                                               \
    }                                                                              \
    ISSUE_B(IT, B);                                                                \
} while (0)

    // fp32 A register prefetch + transform + STS
    float4 pa[4];
    const int arow = tid >> 1;
    const int acg  = (tid & 1) * 16;
#define LOAD_A(IT) do {                                                            \
    const float* p = Af + (size_t)(m0 + arow) * K + (IT) * 32 + acg;               \
    pa[0] = *(const float4*)p;       pa[1] = *(const float4*)(p + 4);              \
    pa[2] = *(const float4*)(p + 8); pa[3] = *(const float4*)(p + 12);             \
} while (0)
#define STS_A(B, IT) do {                                                          \
    const int k0 = (IT) * 32 + acg;                                                \
    __nv_bfloat16 hb[16], lb[16];                                                  \
    const float* vv = (const float*)pa;                                            \
    _Pragma("unroll")                                                              \
    for (int j = 0; j < 16; ++j) {                                                 \
        const float t = fmaxf(vv[j] * sScale[k0 + j] + sShift[k0 + j], 0.f);       \
        bsplit(t, hb[j], lb[j]);                                                   \
    }                                                                              \
    __nv_bfloat16* dh = smem + (B) * BUFU + arow * LDS_ROW + acg;                  \
    __nv_bfloat16* dl = dh + A_SZ;                                                 \
    *(uint4*)dh = *(uint4*)hb; *(uint4*)(dh + 8) = *(uint4*)(hb + 8);              \
    *(uint4*)dl = *(uint4*)lb; *(uint4*)(dl + 8) = *(uint4*)(lb + 8);              \
} while (0)

    if (TR) { LOAD_A(0); ISSUE_B(0, 0); }
    else    { ISSUE_AB(0, 0); }

    for (int it = 0; it < NK; ++it) {
        const int cur = it & 1;
        if (TR) STS_A(cur, it);
        if (it + 1 < NK) {
            if (TR) { ISSUE_B(it + 1, 1 - cur); LOAD_A(it + 1); }
            else    { ISSUE_AB(it + 1, 1 - cur); }
            asm volatile("cp.async.wait_group 1;" ::: "memory");
        } else {
            asm volatile("cp.async.wait_group 0;" ::: "memory");
        }
        __syncthreads();

        const uint32_t sAh_s = sbase + (uint32_t)(cur * BUFU) * 2;
        const uint32_t sAl_s = sAh_s + A_SZ * 2;
        const uint32_t sBh_s = sAh_s + 2 * A_SZ * 2;
        const uint32_t sBl_s = sBh_s + B_SZ * 2;
#pragma unroll
        for (int ks = 0; ks < 2; ++ks) {
            const uint32_t kb = ks * 32;   // 16 bf16 = 32 bytes
            uint32_t ah[4][4], ao[4][4], bb[8][2];
#pragma unroll
            for (int mt = 0; mt < 4; ++mt)
                LDM_X4(ah[mt][0], ah[mt][1], ah[mt][2], ah[mt][3],
                       sAh_s + aoff + (uint32_t)(mt * 16 * LDS_ROW * 2) + kb);
#pragma unroll
            for (int np = 0; np < 4; ++np)
                LDM_X4(bb[2*np][0], bb[2*np][1], bb[2*np+1][0], bb[2*np+1][1],
                       sBh_s + boff + (uint32_t)(np * 16 * LDS_ROW * 2) + kb);
            // pass 1: Ahi * Bhi
#pragma unroll
            for (int mt = 0; mt < 4; ++mt)
#pragma unroll
                for (int nt = 0; nt < 8; ++nt)
                    mma_bf16(acc[mt][nt], ah[mt], bb[nt]);
            // pass 2: Alo * Bhi
#pragma unroll
            for (int mt = 0; mt < 4; ++mt)
                LDM_X4(ao[mt][0], ao[mt][1], ao[mt][2], ao[mt][3],
                       sAl_s + aoff + (uint32_t)(mt * 16 * LDS_ROW * 2) + kb);
#pragma unroll
            for (int mt = 0; mt < 4; ++mt)
#pragma unroll
                for (int nt = 0; nt < 8; ++nt)
                    mma_bf16(acc[mt][nt], ao[mt], bb[nt]);
            // pass 3: Ahi * Blo
#pragma unroll
            for (int np = 0; np < 4; ++np)
                LDM_X4(bb[2*np][0], bb[2*np][1], bb[2*np+1][0], bb[2*np+1][1],
                       sBl_s + boff + (uint32_t)(np * 16 * LDS_ROW * 2) + kb);
#pragma unroll
            for (int mt = 0; mt < 4; ++mt)
#pragma unroll
                for (int nt = 0; nt < 8; ++nt)
                    mma_bf16(acc[mt][nt], ah[mt], bb[nt]);
        }
        __syncthreads();
    }

    // Epilogue: bias, store C, fused deterministic column stats
    float colsum[16], colsq[16];
#pragma unroll
    for (int i = 0; i < 16; ++i) { colsum[i] = 0.f; colsq[i] = 0.f; }

#pragma unroll
    for (int mt = 0; mt < 4; ++mt)
#pragma unroll
        for (int nt = 0; nt < 8; ++nt) {
            const int r   = m0 + wm + mt * 16 + gid;
            const int col = n0 + wn + nt * 8 + 2 * tig;
            const float b0 = bias[col], b1 = bias[col + 1];
            const float v00 = acc[mt][nt][0] + b0, v01 = acc[mt][nt][1] + b1;
            const float v10 = acc[mt][nt][2] + b0, v11 = acc[mt][nt][3] + b1;
            *(float2*)(C + (size_t)r * Nc + col)       = make_float2(v00, v01);
            *(float2*)(C + (size_t)(r + 8) * Nc + col) = make_float2(v10, v11);
            colsum[nt * 2 + 0] += v00 + v10;  colsq[nt * 2 + 0] += v00 * v00 + v10 * v10;
            colsum[nt * 2 + 1] += v01 + v11;  colsq[nt * 2 + 1] += v01 * v01 + v11 * v11;
        }
#pragma unroll
    for (int i = 0; i < 16; ++i) {
#pragma unroll
        for (int off = 16; off >= 4; off >>= 1) {
            colsum[i] += __shfl_down_sync(0xffffffffu, colsum[i], off);
            colsq[i]  += __shfl_down_sync(0xffffffffu, colsq[i],  off);
        }
    }
    __syncthreads();
    float* ssum = (float*)smem;        // [2][256]
    float* ssq  = ssum + 512;
    if (gid == 0) {
        const int mwarp = wid >> 2;
#pragma unroll
        for (int nt = 0; nt < 8; ++nt) {
            const int c = wn + nt * 8 + 2 * tig;
            ssum[mwarp * 256 + c]     = colsum[nt * 2 + 0];
            ssum[mwarp * 256 + c + 1] = colsum[nt * 2 + 1];
            ssq [mwarp * 256 + c]     = colsq[nt * 2 + 0];
            ssq [mwarp * 256 + c + 1] = colsq[nt * 2 + 1];
        }
    }
    __syncthreads();
    if (tid < 256) {
        part[blockIdx.y * 512 + n0 + tid]           = ssum[tid] + ssum[256 + tid];
        part[PART_SQ + blockIdx.y * 512 + n0 + tid] = ssq[tid]  + ssq[256 + tid];
    }
}

// ---------------- all 4 weight transposes + bf16 splits in one launch ----------------
__global__ void wsplit_all(const float* __restrict__ W1a, const float* __restrict__ W1b,
                           const float* __restrict__ W2a, const float* __restrict__ W2b,
                           __nv_bfloat16* __restrict__ w1h, __nv_bfloat16* __restrict__ w1l,
                           __nv_bfloat16* __restrict__ w2h, __nv_bfloat16* __restrict__ w2l,
                           __nv_bfloat16* __restrict__ w3h, __nv_bfloat16* __restrict__ w3l,
                           __nv_bfloat16* __restrict__ w4h, __nv_bfloat16* __restrict__ w4l)
{
    __shared__ float tile[32][33];
    const float* W; __nv_bfloat16 *Wh, *Wl; int K, N;
    switch (blockIdx.z) {
        case 0:  W = W1a; Wh = w1h; Wl = w1l; K = 128; N = 512; break;
        case 1:  W = W1b; Wh = w2h; Wl = w2l; K = 512; N = 256; break;
        case 2:  W = W2a; Wh = w3h; Wl = w3l; K = 256; N = 512; break;
        default: W = W2b; Wh = w4h; Wl = w4l; K = 512; N = 256; break;
    }
    const int n0 = blockIdx.x * 32, k0 = blockIdx.y * 32;
    if (n0 >= N || k0 >= K) return;
    for (int i = threadIdx.y; i < 32; i += 8)
        tile[i][threadIdx.x] = W[(size_t)(k0 + i) * N + n0 + threadIdx.x];
    __syncthreads();
    for (int i = threadIdx.y; i < 32; i += 8) {
        const float v = tile[threadIdx.x][i];
        __nv_bfloat16 h, l;
        bsplit(v, h, l);
        Wh[(size_t)(n0 + i) * K + k0 + threadIdx.x] = h;
        Wl[(size_t)(n0 + i) * K + k0 + threadIdx.x] = l;
    }
}

// ---------------- per-graph aggregation, bf16 hi/lo output ----------------
__global__ void agg_kernel(const float* __restrict__ in, __nv_bfloat16* __restrict__ oh,
                           __nv_bfloat16* __restrict__ ol,
                           const int* __restrict__ ei, int dimtot, int mode,
                           const float* __restrict__ scale, const float* __restrict__ shift,
                           const float* __restrict__ vemb)
{
    __shared__ float agg[NPG * 64];
    __shared__ int   se[2 * EPG];
    const int g  = blockIdx.x;
    const int d0 = blockIdx.y * 64;
    const int t  = threadIdx.x;

    for (int e = t; e < EPG; e += 64) {
        se[e]       = ei[g * EPG + e];
        se[EPG + e] = ei[EDGES + g * EPG + e];
    }
    for (int i = t; i < NPG * 64; i += 64) agg[i] = 0.f;
    __syncthreads();

    const int nb = g * NPG;
    const int d  = d0 + t;
    float sc_ = 0.f, sh_ = 0.f, ve = 0.f;
    if (mode) { sc_ = scale[d]; sh_ = shift[d]; ve = vemb[d]; }

    for (int e = 0; e < EPG; ++e) {
        const int r = se[e] - nb;
        const int c = se[EPG + e] - nb;
        float v = in[(size_t)(nb + r) * dimtot + d];
        if (mode) v = fmaxf(v * sc_ + sh_, 0.f) + ve;
        agg[c * 64 + t] += v;
    }
    __syncthreads();

    for (int n = 0; n < NPG; ++n) {
        float v = in[(size_t)(nb + n) * dimtot + d];
        if (mode) v = fmaxf(v * sc_ + sh_, 0.f) + ve;
        const float h = v + agg[n * 64 + t];
        __nv_bfloat16 hh, ll;
        bsplit(h, hh, ll);
        oh[(size_t)(nb + n) * dimtot + d] = hh;
        ol[(size_t)(nb + n) * dimtot + d] = ll;
    }
}

// ---------------- BN finalize ----------------
__global__ void finalize_kernel(const float* __restrict__ gg, const float* __restrict__ be,
                                const float* __restrict__ part,
                                float* __restrict__ scale, float* __restrict__ shift)
{
    __shared__ float ssum[256], ssq[256];
    const int c = blockIdx.x;
    const int t = threadIdx.x;
    ssum[t] = part[t * 512 + c];
    ssq[t]  = part[PART_SQ + t * 512 + c];
    __syncthreads();
#pragma unroll
    for (int o = 128; o; o >>= 1) {
        if (t < o) { ssum[t] += ssum[t + o]; ssq[t] += ssq[t + o]; }
        __syncthreads();
    }
    if (t == 0) {
        const float mu  = ssum[0] / (float)NNODES;
        const float var = ssq[0] / (float)NNODES - mu * mu;
        const float rs  = rsqrtf(var + BN_EPS);
        const float sc  = gg[c] * rs;
        scale[c] = sc;
        shift[c] = be[c] - mu * sc;
    }
}

// ---------------- per-node edge-logit halves ----------------
__global__ void nodedot_kernel(const float* __restrict__ Xn, const float* __restrict__ Wl,
                               const float* __restrict__ scale, const float* __restrict__ shift,
                               float* __restrict__ sa_o, float* __restrict__ sc_o)
{
    const int w = threadIdx.x >> 5;
    const int l = threadIdx.x & 31;
    const int n = blockIdx.x * 8 + w;
    float sa = 0.f, sc = 0.f;
#pragma unroll
    for (int i = 0; i < 8; ++i) {
        const int d = l + i * 32;
        const float v = Xn[(size_t)n * DD + d] * scale[d] + shift[d];
        sa = fmaf(v, Wl[d], sa);
        sc = fmaf(v, Wl[DD + d], sc);
    }
#pragma unroll
    for (int o = 16; o; o >>= 1) {
        sa += __shfl_down_sync(0xffffffffu, sa, o);
        sc += __shfl_down_sync(0xffffffffu, sc, o);
    }
    if (l == 0) { sa_o[n] = sa; sc_o[n] = sc; }
}

// ---------------- per-edge prediction ----------------
__global__ void pred_kernel(const int* __restrict__ ei, const float* __restrict__ bl,
                            const float* __restrict__ sa, const float* __restrict__ sc,
                            float* __restrict__ out)
{
    const int e = blockIdx.x * 256 + threadIdx.x;
    out[OFF_PRED + e] = sa[ei[e]] + sc[ei[EDGES + e]] + bl[0];
}

// ---------------- per-graph stable descending sort + output scatter ----------------
__device__ __forceinline__ unsigned ordered_f32(float f)
{
    unsigned u = __float_as_uint(f);
    return (u & 0x80000000u) ? ~u : (u | 0x80000000u);
}

__global__ void sort_kernel(const int* __restrict__ ei, float* __restrict__ out)
{
    __shared__ unsigned long long keys[EPG];
    const int g = blockIdx.x;
    const int t = threadIdx.x;
    const float* pred = out + OFF_PRED + (size_t)g * EPG;

    for (int j = t; j < EPG; j += 256) {
        const unsigned u = ordered_f32(pred[j]);
        keys[j] = ((unsigned long long)(~u) << 32) | (unsigned)j;
    }
    __syncthreads();

    for (int k = 2; k <= EPG; k <<= 1) {
        for (int j = k >> 1; j > 0; j >>= 1) {
            for (int i = t; i < EPG; i += 256) {
                const int ixj = i ^ j;
                if (ixj > i) {
                    const bool up = ((i & k) == 0);
                    unsigned long long a = keys[i], b = keys[ixj];
                    if ((a > b) == up) { keys[i] = b; keys[ixj] = a; }
                }
            }
            __syncthreads();
        }
    }

    for (int j = t; j < EPG; j += 256) {
        const int   idx = (int)(keys[j] & 0xffffffffu);
        const float p   = pred[idx];
        const int   s   = ei[g * EPG + idx];
        const int   dst = ei[EDGES + g * EPG + idx];
        if (j < NRES) {
            const int o = g * NRES + j;
            out[OFF_CEI + o]         = (float)s;
            out[OFF_CEI + 65536 + o] = (float)dst;
            out[OFF_CW + o]          = p;
        } else {
            const int o = g * NRES + (j - NRES);
            out[OFF_DEI + o]         = (float)s;
            out[OFF_DEI + 65536 + o] = (float)dst;
            out[OFF_DW + o]          = -p;
        }
    }
}

// ---------------- launch ----------------
extern "C" void kernel_launch(void* const* d_in, const int* in_sizes, int n_in,
                              void* d_out, int out_size)
{
    const float* x    = (const float*)d_in[0];
    const int*   ei   = (const int*)  d_in[1];
    const float* vemb = (const float*)d_in[3];
    const float* W1a  = (const float*)d_in[4];
    const float* b1a  = (const float*)d_in[5];
    const float* g1a  = (const float*)d_in[6];
    const float* be1a = (const float*)d_in[7];
    const float* W1b  = (const float*)d_in[8];
    const float* b1b  = (const float*)d_in[9];
    const float* g1   = (const float*)d_in[10];
    const float* be1  = (const float*)d_in[11];
    const float* W2a  = (const float*)d_in[12];
    const float* b2a  = (const float*)d_in[13];
    const float* g2a  = (const float*)d_in[14];
    const float* be2a = (const float*)d_in[15];
    const float* W2b  = (const float*)d_in[16];
    const float* b2b  = (const float*)d_in[17];
    const float* g2   = (const float*)d_in[18];
    const float* be2  = (const float*)d_in[19];
    const float* Wl   = (const float*)d_in[20];
    const float* bl   = (const float*)d_in[21];
    float* out = (float*)d_out;

    float *pz, *po1, *ppart, *pscale, *pshift, *psa, *psc;
    __nv_bfloat16 *h1h, *h1l, *h2h, *h2l;
    __nv_bfloat16 *w1h, *w1l, *w2h, *w2l, *w3h, *w3l, *w4h, *w4l;
    cudaGetSymbolAddress((void**)&pz,     g_z);
    cudaGetSymbolAddress((void**)&po1,    g_o1);
    cudaGetSymbolAddress((void**)&ppart,  g_part);
    cudaGetSymbolAddress((void**)&pscale, g_scale);
    cudaGetSymbolAddress((void**)&pshift, g_shift);
    cudaGetSymbolAddress((void**)&psa,    g_sa);
    cudaGetSymbolAddress((void**)&psc,    g_sc);
    cudaGetSymbolAddress((void**)&h1h, g_h1h); cudaGetSymbolAddress((void**)&h1l, g_h1l);
    cudaGetSymbolAddress((void**)&h2h, g_h2h); cudaGetSymbolAddress((void**)&h2l, g_h2l);
    cudaGetSymbolAddress((void**)&w1h, g_w1h); cudaGetSymbolAddress((void**)&w1l, g_w1l);
    cudaGetSymbolAddress((void**)&w2h, g_w2h); cudaGetSymbolAddress((void**)&w2l, g_w2l);
    cudaGetSymbolAddress((void**)&w3h, g_w3h); cudaGetSymbolAddress((void**)&w3l, g_w3l);
    cudaGetSymbolAddress((void**)&w4h, g_w4h); cudaGetSymbolAddress((void**)&w4l, g_w4l);

    cudaFuncSetAttribute(gemm_bf16_kernel<false>, cudaFuncAttributeMaxDynamicSharedMemorySize, GEMM_SMEM);
    cudaFuncSetAttribute(gemm_bf16_kernel<true>,  cudaFuncAttributeMaxDynamicSharedMemorySize, GEMM_SMEM);

    // all weight transposes + splits in one launch
    wsplit_all<<<dim3(16, 16, 4), dim3(32, 8)>>>(W1a, W1b, W2a, W2b,
                                                 w1h, w1l, w2h, w2l, w3h, w3l, w4h, w4l);

    // Layer 1
    agg_kernel<<<dim3(BGR, DIN / 64), 64>>>(x, h1h, h1l, ei, DIN, 0, nullptr, nullptr, nullptr);
    gemm_bf16_kernel<false><<<dim3(2, 256), 256, GEMM_SMEM>>>(
        h1h, h1l, nullptr, nullptr, nullptr, w1h, w1l, b1a, pz, 128, 512, ppart);
    finalize_kernel<<<512, 256>>>(g1a, be1a, ppart, pscale, pshift);
    gemm_bf16_kernel<true><<<dim3(1, 256), 256, GEMM_SMEM>>>(
        nullptr, nullptr, pz, pscale, pshift, w2h, w2l, b1b, po1, 512, 256, ppart);
    finalize_kernel<<<256, 256>>>(g1, be1, ppart, pscale, pshift);

    // Layer 2 (post = relu(bn(o1)) + vemb fused into aggregation)
    agg_kernel<<<dim3(BGR, DD / 64), 64>>>(po1, h2h, h2l, ei, DD, 1, pscale, pshift, vemb);
    gemm_bf16_kernel<false><<<dim3(2, 256), 256, GEMM_SMEM>>>(
        h2h, h2l, nullptr, nullptr, nullptr, w3h, w3l, b2a, pz, 256, 512, ppart);
    finalize_kernel<<<512, 256>>>(g2a, be2a, ppart, pscale, pshift);
    gemm_bf16_kernel<true><<<dim3(1, 256), 256, GEMM_SMEM>>>(
        nullptr, nullptr, pz, pscale, pshift, w4h, w4l, b2b, po1, 512, 256, ppart);
    finalize_kernel<<<256, 256>>>(g2, be2, ppart, pscale, pshift);

    // Edge scores + per-graph stable top-k split
    nodedot_kernel<<<NNODES / 8, 256>>>(po1, Wl, pscale, pshift, psa, psc);
    pred_kernel<<<EDGES / 256, 256>>>(ei, bl, psa, psc, out);
    sort_kernel<<<BGR, 256>>>(ei, out);
}

// round 6
// speedup vs baseline: 1.5811x; 1.0216x over previous
#include <cuda_runtime.h>
#include <cuda_bf16.h>
#include <math.h>
#include <stdint.h>

// Problem constants
#define NNODES 32768
#define DIN    128
#define DD     256
#define D2     512
#define EDGES  131072
#define BGR    256
#define EPG    512
#define NPG    128
#define NRES   256
#define BN_EPS 1e-5f

// Output layout (float32, 524288 elems)
#define OFF_CEI   0
#define OFF_CW    131072
#define OFF_DEI   196608
#define OFF_DW    327680
#define OFF_PRED  393216

// ---------------- scratch (device globals; no allocation) ----------------
__device__ __align__(16) float g_z [NNODES * D2];
__device__ __align__(16) float g_o1[NNODES * DD];
__device__ __align__(16) float g_part[2 * 256 * 512];   // [ch][mblk] layout, coalesced finalize
#define PART_SQ (256 * 512)
__device__ float g_scale[512];
__device__ float g_shift[512];
__device__ float g_sa[NNODES];
__device__ float g_sc[NNODES];
__device__ __align__(16) __nv_bfloat16 g_h1h[NNODES * DIN], g_h1l[NNODES * DIN];
__device__ __align__(16) __nv_bfloat16 g_h2h[NNODES * DD],  g_h2l[NNODES * DD];
__device__ __align__(16) __nv_bfloat16 g_w1h[D2 * DIN], g_w1l[D2 * DIN];
__device__ __align__(16) __nv_bfloat16 g_w2h[DD * D2],  g_w2l[DD * D2];
__device__ __align__(16) __nv_bfloat16 g_w3h[D2 * DD],  g_w3l[D2 * DD];
__device__ __align__(16) __nv_bfloat16 g_w4h[DD * D2],  g_w4l[DD * D2];

// ---------------- helpers ----------------
__device__ __forceinline__ void bsplit(float v, __nv_bfloat16& h, __nv_bfloat16& l)
{
    h = __float2bfloat16(v);
    l = __float2bfloat16(v - __bfloat162float(h));
}

__device__ __forceinline__ void mma_bf16(float* c, const uint32_t* a, const uint32_t* b)
{
    asm volatile("mma.sync.aligned.m16n8k16.row.col.f32.bf16.bf16.f32 "
                 "{%0,%1,%2,%3}, {%4,%5,%6,%7}, {%8,%9}, {%0,%1,%2,%3};"
                 : "+f"(c[0]), "+f"(c[1]), "+f"(c[2]), "+f"(c[3])
                 : "r"(a[0]), "r"(a[1]), "r"(a[2]), "r"(a[3]), "r"(b[0]), "r"(b[1]));
}

#define CP16(dst, src) \
    asm volatile("cp.async.cg.shared.global [%0], [%1], 16;" :: "r"(dst), "l"(src) : "memory")
#define LDM_X4(r0, r1, r2, r3, addr) \
    asm volatile("ldmatrix.sync.aligned.m8n8.x4.shared.b16 {%0,%1,%2,%3}, [%4];" \
                 : "=r"(r0), "=r"(r1), "=r"(r2), "=r"(r3) : "r"(addr))
#define COMMIT() asm volatile("cp.async.commit_group;" ::: "memory")

// ---------------- bf16x3 GEMM, 3-stage pipeline, single sync/iter ----------------
// C[M,Nc] = (Ah+Al)[M,K] @ (Bh+Bl)[Nc,K]^T + bias. CTA 128x256, BK=32, 8 warps (2m x 4n).
// TR=true: A produced from fp32 Af with relu(a*scale+shift), split in registers.
#define LDS_ROW 40
#define A_SZ (128 * LDS_ROW)
#define B_SZ (256 * LDS_ROW)
#define BUFU (2 * A_SZ + 2 * B_SZ)            // bf16 units per stage (30720)
#define NSTAGE 3
#define GEMM_SMEM (NSTAGE * BUFU * 2 + 4096)  // 188416 B

template<bool TR>
__global__ __launch_bounds__(256, 1)
void gemm_bf16_kernel(const __nv_bfloat16* __restrict__ Ah, const __nv_bfloat16* __restrict__ Al,
                      const float* __restrict__ Af, const float* __restrict__ tsc,
                      const float* __restrict__ tsh,
                      const __nv_bfloat16* __restrict__ Bh, const __nv_bfloat16* __restrict__ Bl,
                      const float* __restrict__ bias, float* __restrict__ C,
                      int K, int Nc, float* __restrict__ part)
{
    extern __shared__ __align__(16) __nv_bfloat16 smem[];
    float* sScale = (float*)(smem + NSTAGE * BUFU);
    float* sShift = sScale + 512;
    const int tid  = threadIdx.x;
    const int lane = tid & 31;
    const int wid  = tid >> 5;
    const int gid  = lane >> 2, tig = lane & 3;
    const int wm   = (wid >> 2) * 64;
    const int wn   = (wid & 3) * 64;
    const int n0   = blockIdx.x * 256;
    const int m0   = blockIdx.y * 128;
    const int NK   = K >> 5;
    const uint32_t sbase = (uint32_t)__cvta_generic_to_shared(smem);

    if (TR) {
        for (int i = tid; i < K; i += 256) { sScale[i] = tsc[i]; sShift[i] = tsh[i]; }
        __syncthreads();
    }

    const uint32_t aoff = (uint32_t)(((wm + (lane & 15)) * LDS_ROW + ((lane >> 4) << 3)) * 2);
    const uint32_t boff = (uint32_t)(((wn + (lane & 7) + (((lane >> 4) & 1) << 3)) * LDS_ROW
                                      + (((lane >> 3) & 1) << 3)) * 2);

    float acc[4][8][4];
#pragma unroll
    for (int mt = 0; mt < 4; ++mt)
#pragma unroll
        for (int nt = 0; nt < 8; ++nt)
#pragma unroll
            for (int j = 0; j < 4; ++j) acc[mt][nt][j] = 0.f;

#define ISSUE_B(IT, S) do {                                                        \
    const int koff = (IT) * 32;                                                    \
    for (int c = tid; c < 2048; c += 256) {                                        \
        const int row = (c & 1023) >> 2, q = c & 3;                                \
        const __nv_bfloat16* src = (c < 1024 ? Bh : Bl) + (size_t)(n0 + row) * K + koff + q * 8; \
        const uint32_t doff = (uint32_t)((S) * BUFU + 2 * A_SZ + (c < 1024 ? 0 : B_SZ) + row * LDS_ROW + q * 8); \
        CP16(sbase + doff * 2, src);                                               \
    }                                                                              \
} while (0)

#define ISSUE_AB(IT, S) do {                                                       \
    const int koff = (IT) * 32;                                                    \
    for (int c = tid; c < 1024; c += 256) {                                        \
        const int row = (c & 511) >> 2, q = c & 3;                                 \
        const __nv_bfloat16* src = (c < 512 ? Ah : Al) + (size_t)(m0 + row) * K + koff + q * 8; \
        const uint32_t doff = (uint32_t)((S) * BUFU + (c < 512 ? 0 : A_SZ) + row * LDS_ROW + q * 8); \
        CP16(sbase + doff * 2, src);                                               \
    }                                                                              \
    ISSUE_B(IT, S);                                                                \
} while (0)

    float4 pa[4];
    const int arow = tid >> 1;
    const int acg  = (tid & 1) * 16;
#define LOAD_A(IT) do {                                                            \
    const float* p = Af + (size_t)(m0 + arow) * K + (IT) * 32 + acg;               \
    pa[0] = *(const float4*)p;       pa[1] = *(const float4*)(p + 4);              \
    pa[2] = *(const float4*)(p + 8); pa[3] = *(const float4*)(p + 12);             \
} while (0)
#define STS_A(S, IT) do {                                                          \
    const int k0 = (IT) * 32 + acg;                                                \
    __nv_bfloat16 hb[16], lb[16];                                                  \
    const float* vv = (const float*)pa;                                            \
    _Pragma("unroll")                                                              \
    for (int j = 0; j < 16; ++j) {                                                 \
        const float t = fmaxf(vv[j] * sScale[k0 + j] + sShift[k0 + j], 0.f);       \
        bsplit(t, hb[j], lb[j]);                                                   \
    }                                                                              \
    __nv_bfloat16* dh = smem + (S) * BUFU + arow * LDS_ROW + acg;                  \
    __nv_bfloat16* dl = dh + A_SZ;                                                 \
    *(uint4*)dh = *(uint4*)hb; *(uint4*)(dh + 8) = *(uint4*)(hb + 8);              \
    *(uint4*)dl = *(uint4*)lb; *(uint4*)(dl + 8) = *(uint4*)(lb + 8);              \
} while (0)

    // prologue: stages 0 and 1 in flight
    if (TR) { LOAD_A(0); ISSUE_B(0, 0); COMMIT(); ISSUE_B(1, 1); COMMIT(); }
    else    { ISSUE_AB(0, 0); COMMIT(); ISSUE_AB(1, 1); COMMIT(); }

    for (int it = 0; it < NK; ++it) {
        const int cur = it % NSTAGE;
        if (TR) STS_A(cur, it);                 // targets cur; slow warps read (it-1)%3 != cur
        asm volatile("cp.async.wait_group 1;" ::: "memory");   // group `it` landed
        __syncthreads();                        // readers of (it-1)%3 done; STS_A visible
        {
            const int nx = it + 2;
            if (nx < NK) {
                if (TR) ISSUE_B(nx, nx % NSTAGE);
                else    ISSUE_AB(nx, nx % NSTAGE);
            }
            COMMIT();                           // empty commit keeps group accounting uniform
        }
        if (TR && it + 1 < NK) LOAD_A(it + 1);

        const uint32_t sAh_s = sbase + (uint32_t)(cur * BUFU) * 2;
        const uint32_t sAl_s = sAh_s + A_SZ * 2;
        const uint32_t sBh_s = sAh_s + 2 * A_SZ * 2;
        const uint32_t sBl_s = sBh_s + B_SZ * 2;
#pragma unroll
        for (int ks = 0; ks < 2; ++ks) {
            const uint32_t kb = ks * 32;
            uint32_t ah[4][4], ao[4][4], bb[8][2];
#pragma unroll
            for (int mt = 0; mt < 4; ++mt)
                LDM_X4(ah[mt][0], ah[mt][1], ah[mt][2], ah[mt][3],
                       sAh_s + aoff + (uint32_t)(mt * 16 * LDS_ROW * 2) + kb);
#pragma unroll
            for (int np = 0; np < 4; ++np)
                LDM_X4(bb[2*np][0], bb[2*np][1], bb[2*np+1][0], bb[2*np+1][1],
                       sBh_s + boff + (uint32_t)(np * 16 * LDS_ROW * 2) + kb);
#pragma unroll
            for (int mt = 0; mt < 4; ++mt)
#pragma unroll
                for (int nt = 0; nt < 8; ++nt)
                    mma_bf16(acc[mt][nt], ah[mt], bb[nt]);
#pragma unroll
            for (int mt = 0; mt < 4; ++mt)
                LDM_X4(ao[mt][0], ao[mt][1], ao[mt][2], ao[mt][3],
                       sAl_s + aoff + (uint32_t)(mt * 16 * LDS_ROW * 2) + kb);
#pragma unroll
            for (int mt = 0; mt < 4; ++mt)
#pragma unroll
                for (int nt = 0; nt < 8; ++nt)
                    mma_bf16(acc[mt][nt], ao[mt], bb[nt]);
#pragma unroll
            for (int np = 0; np < 4; ++np)
                LDM_X4(bb[2*np][0], bb[2*np][1], bb[2*np+1][0], bb[2*np+1][1],
                       sBl_s + boff + (uint32_t)(np * 16 * LDS_ROW * 2) + kb);
#pragma unroll
            for (int mt = 0; mt < 4; ++mt)
#pragma unroll
                for (int nt = 0; nt < 8; ++nt)
                    mma_bf16(acc[mt][nt], ah[mt], bb[nt]);
        }
    }

    // Epilogue: bias, store C, fused deterministic column stats
    __syncthreads();
    float colsum[16], colsq[16];
#pragma unroll
    for (int i = 0; i < 16; ++i) { colsum[i] = 0.f; colsq[i] = 0.f; }

#pragma unroll
    for (int mt = 0; mt < 4; ++mt)
#pragma unroll
        for (int nt = 0; nt < 8; ++nt) {
            const int r   = m0 + wm + mt * 16 + gid;
            const int col = n0 + wn + nt * 8 + 2 * tig;
            const float b0 = bias[col], b1 = bias[col + 1];
            const float v00 = acc[mt][nt][0] + b0, v01 = acc[mt][nt][1] + b1;
            const float v10 = acc[mt][nt][2] + b0, v11 = acc[mt][nt][3] + b1;
            *(float2*)(C + (size_t)r * Nc + col)       = make_float2(v00, v01);
            *(float2*)(C + (size_t)(r + 8) * Nc + col) = make_float2(v10, v11);
            colsum[nt * 2 + 0] += v00 + v10;  colsq[nt * 2 + 0] += v00 * v00 + v10 * v10;
            colsum[nt * 2 + 1] += v01 + v11;  colsq[nt * 2 + 1] += v01 * v01 + v11 * v11;
        }
#pragma unroll
    for (int i = 0; i < 16; ++i) {
#pragma unroll
        for (int off = 16; off >= 4; off >>= 1) {
            colsum[i] += __shfl_down_sync(0xffffffffu, colsum[i], off);
            colsq[i]  += __shfl_down_sync(0xffffffffu, colsq[i],  off);
        }
    }
    float* ssum = (float*)smem;        // [2][256]
    float* ssq  = ssum + 512;
    if (gid == 0) {
        const int mwarp = wid >> 2;
#pragma unroll
        for (int nt = 0; nt < 8; ++nt) {
            const int c = wn + nt * 8 + 2 * tig;
            ssum[mwarp * 256 + c]     = colsum[nt * 2 + 0];
            ssum[mwarp * 256 + c + 1] = colsum[nt * 2 + 1];
            ssq [mwarp * 256 + c]     = colsq[nt * 2 + 0];
            ssq [mwarp * 256 + c + 1] = colsq[nt * 2 + 1];
        }
    }
    __syncthreads();
    if (tid < 256) {
        // transposed layout: part[channel * 256 + mblock] (coalesced finalize reads)
        part[(size_t)(n0 + tid) * 256 + blockIdx.y]           = ssum[tid] + ssum[256 + tid];
        part[PART_SQ + (size_t)(n0 + tid) * 256 + blockIdx.y] = ssq[tid]  + ssq[256 + tid];
    }
}

// ---------------- all 4 weight transposes + bf16 splits in one launch ----------------
__global__ void wsplit_all(const float* __restrict__ W1a, const float* __restrict__ W1b,
                           const float* __restrict__ W2a, const float* __restrict__ W2b,
                           __nv_bfloat16* __restrict__ w1h, __nv_bfloat16* __restrict__ w1l,
                           __nv_bfloat16* __restrict__ w2h, __nv_bfloat16* __restrict__ w2l,
                           __nv_bfloat16* __restrict__ w3h, __nv_bfloat16* __restrict__ w3l,
                           __nv_bfloat16* __restrict__ w4h, __nv_bfloat16* __restrict__ w4l)
{
    __shared__ float tile[32][33];
    const float* W; __nv_bfloat16 *Wh, *Wl; int K, N;
    switch (blockIdx.z) {
        case 0:  W = W1a; Wh = w1h; Wl = w1l; K = 128; N = 512; break;
        case 1:  W = W1b; Wh = w2h; Wl = w2l; K = 512; N = 256; break;
        case 2:  W = W2a; Wh = w3h; Wl = w3l; K = 256; N = 512; break;
        default: W = W2b; Wh = w4h; Wl = w4l; K = 512; N = 256; break;
    }
    const int n0 = blockIdx.x * 32, k0 = blockIdx.y * 32;
    if (n0 >= N || k0 >= K) return;
    for (int i = threadIdx.y; i < 32; i += 8)
        tile[i][threadIdx.x] = W[(size_t)(k0 + i) * N + n0 + threadIdx.x];
    __syncthreads();
    for (int i = threadIdx.y; i < 32; i += 8) {
        const float v = tile[threadIdx.x][i];
        __nv_bfloat16 h, l;
        bsplit(v, h, l);
        Wh[(size_t)(n0 + i) * K + k0 + threadIdx.x] = h;
        Wl[(size_t)(n0 + i) * K + k0 + threadIdx.x] = l;
    }
}

// ---------------- per-graph aggregation, bf16 hi/lo output ----------------
__global__ void agg_kernel(const float* __restrict__ in, __nv_bfloat16* __restrict__ oh,
                           __nv_bfloat16* __restrict__ ol,
                           const int* __restrict__ ei, int dimtot, int mode,
                           const float* __restrict__ scale, const float* __restrict__ shift,
                           const float* __restrict__ vemb)
{
    __shared__ float agg[NPG * 64];
    __shared__ int   se[2 * EPG];
    const int g  = blockIdx.x;
    const int d0 = blockIdx.y * 64;
    const int t  = threadIdx.x;

    for (int e = t; e < EPG; e += 64) {
        se[e]       = ei[g * EPG + e];
        se[EPG + e] = ei[EDGES + g * EPG + e];
    }
    for (int i = t; i < NPG * 64; i += 64) agg[i] = 0.f;
    __syncthreads();

    const int nb = g * NPG;
    const int d  = d0 + t;
    float sc_ = 0.f, sh_ = 0.f, ve = 0.f;
    if (mode) { sc_ = scale[d]; sh_ = shift[d]; ve = vemb[d]; }

    for (int e = 0; e < EPG; ++e) {
        const int r = se[e] - nb;
        const int c = se[EPG + e] - nb;
        float v = in[(size_t)(nb + r) * dimtot + d];
        if (mode) v = fmaxf(v * sc_ + sh_, 0.f) + ve;
        agg[c * 64 + t] += v;
    }
    __syncthreads();

    for (int n = 0; n < NPG; ++n) {
        float v = in[(size_t)(nb + n) * dimtot + d];
        if (mode) v = fmaxf(v * sc_ + sh_, 0.f) + ve;
        const float h = v + agg[n * 64 + t];
        __nv_bfloat16 hh, ll;
        bsplit(h, hh, ll);
        oh[(size_t)(nb + n) * dimtot + d] = hh;
        ol[(size_t)(nb + n) * dimtot + d] = ll;
    }
}

// ---------------- BN finalize (coalesced part reads) ----------------
__global__ void finalize_kernel(const float* __restrict__ gg, const float* __restrict__ be,
                                const float* __restrict__ part,
                                float* __restrict__ scale, float* __restrict__ shift)
{
    __shared__ float ssum[256], ssq[256];
    const int c = blockIdx.x;
    const int t = threadIdx.x;
    ssum[t] = part[(size_t)c * 256 + t];
    ssq[t]  = part[PART_SQ + (size_t)c * 256 + t];
    __syncthreads();
#pragma unroll
    for (int o = 128; o; o >>= 1) {
        if (t < o) { ssum[t] += ssum[t + o]; ssq[t] += ssq[t + o]; }
        __syncthreads();
    }
    if (t == 0) {
        const float mu  = ssum[0] / (float)NNODES;
        const float var = ssq[0] / (float)NNODES - mu * mu;
        const float rs  = rsqrtf(var + BN_EPS);
        const float sc  = gg[c] * rs;
        scale[c] = sc;
        shift[c] = be[c] - mu * sc;
    }
}

// ---------------- per-node edge-logit halves ----------------
__global__ void nodedot_kernel(const float* __restrict__ Xn, const float* __restrict__ Wl,
                               const float* __restrict__ scale, const float* __restrict__ shift,
                               float* __restrict__ sa_o, float* __restrict__ sc_o)
{
    const int w = threadIdx.x >> 5;
    const int l = threadIdx.x & 31;
    const int n = blockIdx.x * 8 + w;
    float sa = 0.f, sc = 0.f;
#pragma unroll
    for (int i = 0; i < 8; ++i) {
        const int d = l + i * 32;
        const float v = Xn[(size_t)n * DD + d] * scale[d] + shift[d];
        sa = fmaf(v, Wl[d], sa);
        sc = fmaf(v, Wl[DD + d], sc);
    }
#pragma unroll
    for (int o = 16; o; o >>= 1) {
        sa += __shfl_down_sync(0xffffffffu, sa, o);
        sc += __shfl_down_sync(0xffffffffu, sc, o);
    }
    if (l == 0) { sa_o[n] = sa; sc_o[n] = sc; }
}

// ---------------- per-edge prediction ----------------
__global__ void pred_kernel(const int* __restrict__ ei, const float* __restrict__ bl,
                            const float* __restrict__ sa, const float* __restrict__ sc,
                            float* __restrict__ out)
{
    const int e = blockIdx.x * 256 + threadIdx.x;
    out[OFF_PRED + e] = sa[ei[e]] + sc[ei[EDGES + e]] + bl[0];
}

// ---------------- per-graph stable descending sort + output scatter ----------------
__device__ __forceinline__ unsigned ordered_f32(float f)
{
    unsigned u = __float_as_uint(f);
    return (u & 0x80000000u) ? ~u : (u | 0x80000000u);
}

__global__ void sort_kernel(const int* __restrict__ ei, float* __restrict__ out)
{
    __shared__ unsigned long long keys[EPG];
    const int g = blockIdx.x;
    const int t = threadIdx.x;
    const float* pred = out + OFF_PRED + (size_t)g * EPG;

    for (int j = t; j < EPG; j += 256) {
        const unsigned u = ordered_f32(pred[j]);
        keys[j] = ((unsigned long long)(~u) << 32) | (unsigned)j;
    }
    __syncthreads();

    for (int k = 2; k <= EPG; k <<= 1) {
        for (int j = k >> 1; j > 0; j >>= 1) {
            for (int i = t; i < EPG; i += 256) {
                const int ixj = i ^ j;
                if (ixj > i) {
                    const bool up = ((i & k) == 0);
                    unsigned long long a = keys[i], b = keys[ixj];
                    if ((a > b) == up) { keys[i] = b; keys[ixj] = a; }
                }
            }
            __syncthreads();
        }
    }

    for (int j = t; j < EPG; j += 256) {
        const int   idx = (int)(keys[j] & 0xffffffffu);
        const float p   = pred[idx];
        const int   s   = ei[g * EPG + idx];
        const int   dst = ei[EDGES + g * EPG + idx];
        if (j < NRES) {
            const int o = g * NRES + j;
            out[OFF_CEI + o]         = (float)s;
            out[OFF_CEI + 65536 + o] = (float)dst;
            out[OFF_CW + o]          = p;
        } else {
            const int o = g * NRES + (j - NRES);
            out[OFF_DEI + o]         = (float)s;
            out[OFF_DEI + 65536 + o] = (float)dst;
            out[OFF_DW + o]          = -p;
        }
    }
}

// ---------------- launch ----------------
extern "C" void kernel_launch(void* const* d_in, const int* in_sizes, int n_in,
                              void* d_out, int out_size)
{
    const float* x    = (const float*)d_in[0];
    const int*   ei   = (const int*)  d_in[1];
    const float* vemb = (const float*)d_in[3];
    const float* W1a  = (const float*)d_in[4];
    const float* b1a  = (const float*)d_in[5];
    const float* g1a  = (const float*)d_in[6];
    const float* be1a = (const float*)d_in[7];
    const float* W1b  = (const float*)d_in[8];
    const float* b1b  = (const float*)d_in[9];
    const float* g1   = (const float*)d_in[10];
    const float* be1  = (const float*)d_in[11];
    const float* W2a  = (const float*)d_in[12];
    const float* b2a  = (const float*)d_in[13];
    const float* g2a  = (const float*)d_in[14];
    const float* be2a = (const float*)d_in[15];
    const float* W2b  = (const float*)d_in[16];
    const float* b2b  = (const float*)d_in[17];
    const float* g2   = (const float*)d_in[18];
    const float* be2  = (const float*)d_in[19];
    const float* Wl   = (const float*)d_in[20];
    const float* bl   = (const float*)d_in[21];
    float* out = (float*)d_out;

    float *pz, *po1, *ppart, *pscale, *pshift, *psa, *psc;
    __nv_bfloat16 *h1h, *h1l, *h2h, *h2l;
    __nv_bfloat16 *w1h, *w1l, *w2h, *w2l, *w3h, *w3l, *w4h, *w4l;
    cudaGetSymbolAddress((void**)&pz,     g_z);
    cudaGetSymbolAddress((void**)&po1,    g_o1);
    cudaGetSymbolAddress((void**)&ppart,  g_part);
    cudaGetSymbolAddress((void**)&pscale, g_scale);
    cudaGetSymbolAddress((void**)&pshift, g_shift);
    cudaGetSymbolAddress((void**)&psa,    g_sa);
    cudaGetSymbolAddress((void**)&psc,    g_sc);
    cudaGetSymbolAddress((void**)&h1h, g_h1h); cudaGetSymbolAddress((void**)&h1l, g_h1l);
    cudaGetSymbolAddress((void**)&h2h, g_h2h); cudaGetSymbolAddress((void**)&h2l, g_h2l);
    cudaGetSymbolAddress((void**)&w1h, g_w1h); cudaGetSymbolAddress((void**)&w1l, g_w1l);
    cudaGetSymbolAddress((void**)&w2h, g_w2h); cudaGetSymbolAddress((void**)&w2l, g_w2l);
    cudaGetSymbolAddress((void**)&w3h, g_w3h); cudaGetSymbolAddress((void**)&w3l, g_w3l);
    cudaGetSymbolAddress((void**)&w4h, g_w4h); cudaGetSymbolAddress((void**)&w4l, g_w4l);

    cudaFuncSetAttribute(gemm_bf16_kernel<false>, cudaFuncAttributeMaxDynamicSharedMemorySize, GEMM_SMEM);
    cudaFuncSetAttribute(gemm_bf16_kernel<true>,  cudaFuncAttributeMaxDynamicSharedMemorySize, GEMM_SMEM);

    wsplit_all<<<dim3(16, 16, 4), dim3(32, 8)>>>(W1a, W1b, W2a, W2b,
                                                 w1h, w1l, w2h, w2l, w3h, w3l, w4h, w4l);

    // Layer 1
    agg_kernel<<<dim3(BGR, DIN / 64), 64>>>(x, h1h, h1l, ei, DIN, 0, nullptr, nullptr, nullptr);
    gemm_bf16_kernel<false><<<dim3(2, 256), 256, GEMM_SMEM>>>(
        h1h, h1l, nullptr, nullptr, nullptr, w1h, w1l, b1a, pz, 128, 512, ppart);
    finalize_kernel<<<512, 256>>>(g1a, be1a, ppart, pscale, pshift);
    gemm_bf16_kernel<true><<<dim3(1, 256), 256, GEMM_SMEM>>>(
        nullptr, nullptr, pz, pscale, pshift, w2h, w2l, b1b, po1, 512, 256, ppart);
    finalize_kernel<<<256, 256>>>(g1, be1, ppart, pscale, pshift);

    // Layer 2
    agg_kernel<<<dim3(BGR, DD / 64), 64>>>(po1, h2h, h2l, ei, DD, 1, pscale, pshift, vemb);
    gemm_bf16_kernel<false><<<dim3(2, 256), 256, GEMM_SMEM>>>(
        h2h, h2l, nullptr, nullptr, nullptr, w3h, w3l, b2a, pz, 256, 512, ppart);
    finalize_kernel<<<512, 256>>>(g2a, be2a, ppart, pscale, pshift);
    gemm_bf16_kernel<true><<<dim3(1, 256), 256, GEMM_SMEM>>>(
        nullptr, nullptr, pz, pscale, pshift, w4h, w4l, b2b, po1, 512, 256, ppart);
    finalize_kernel<<<256, 256>>>(g2, be2, ppart, pscale, pshift);

    // Edge scores + per-graph stable top-k split
    nodedot_kernel<<<NNODES / 8, 256>>>(po1, Wl, pscale, pshift, psa, psc);
    pred_kernel<<<EDGES / 256, 256>>>(ei, bl, psa, psc, out);
    sort_kernel<<<BGR, 256>>>(ei, out);
}